// round 6
// baseline (speedup 1.0000x reference)
#include <cuda_runtime.h>
#include <math.h>

// Geometry (fixed by the problem)
#define NPIX   401408        // 32*112*112
#define DIM    256
#define NCLS   4
#define NSUB   2
#define IMG    12544         // 112*112

// d_out layout: nearest_img | proto_logits | proto_target | new_protos
#define OUT_LOGITS  (NPIX * NCLS)                 // 1605632
#define OUT_TARGET  (OUT_LOGITS + NPIX * 8)       // 4816896
#define OUT_PROTOS  (OUT_TARGET + NPIX)           // 5218304

// ---------------- device scratch (no allocation allowed) ----------------
__device__ double        g_s[3][NCLS][NSUB];     // exp-sum reductions per sinkhorn iter
__device__ double        g_alpha[3][NCLS][NSUB]; // row scalings after each iteration
__device__ int           g_Bn[NCLS];             // per-class pixel counts
__device__ float         g_facc[8][DIM];         // masked feature sums [c*2+m][d]
__device__ int           g_cnt[8];               // assignment counts  [c*2+m]
__device__ float         g_protos[8][DIM];       // l2-normalized prototypes, row = k*2+m
__device__ unsigned char g_correct[NPIX];

__device__ __forceinline__ float wsum(float v) {
#pragma unroll
    for (int o = 16; o; o >>= 1) v += __shfl_xor_sync(0xffffffffu, v, o);
    return v;
}

// ---------------- K0: zero scratch + normalize prototypes ----------------
__global__ void k_init(const float* __restrict__ protos) {
    int tid = threadIdx.x;
    if (tid < 24) ((double*)g_s)[tid] = 0.0;
    if (tid < NCLS) g_Bn[tid] = 0;
    if (tid < 8)    g_cnt[tid] = 0;
    for (int t = tid; t < 8 * DIM; t += blockDim.x) ((float*)g_facc)[t] = 0.f;

    int w = tid >> 5, lane = tid & 31;
    float p[8]; float ss = 0.f;
#pragma unroll
    for (int i = 0; i < 8; i++) { p[i] = protos[w * DIM + lane + 32 * i]; ss += p[i] * p[i]; }
    ss = wsum(ss);
    float inv = 1.0f / fmaxf(sqrtf(ss), 1e-12f);
#pragma unroll
    for (int i = 0; i < 8; i++) g_protos[w][lane + 32 * i] = p[i] * inv;
}

// ---------------- K1: main fused pass over out_feat ----------------
__global__ void __launch_bounds__(256) k_main(
    const float* __restrict__ feat_in, const int* __restrict__ label,
    const float* __restrict__ fg, const float* __restrict__ fb,
    const float* __restrict__ mg, const float* __restrict__ mb,
    float* __restrict__ out)
{
    __shared__ float  sg[DIM], sb[DIM];
    __shared__ float  sprot[8][DIM];
    __shared__ float  smg[4], smb[4];
    __shared__ float  stage[4][32];
    __shared__ double ss1[NCLS][NSUB];
    __shared__ int    sbn[NCLS];

    int tid = threadIdx.x;
    sg[tid] = fg[tid]; sb[tid] = fb[tid];
    for (int t = tid; t < 8 * DIM; t += 256) ((float*)sprot)[t] = ((const float*)g_protos)[t];
    if (tid < 4) { smg[tid] = mg[tid]; smb[tid] = mb[tid]; sbn[tid] = 0; }
    if (tid < 8) ((double*)ss1)[tid] = 0.0;
    __syncthreads();

    int w = tid >> 5, lane = tid & 31;
    float* logits = out + OUT_LOGITS;
    const int nchunks = NPIX / 32;

    for (int chunk = blockIdx.x; chunk < nchunks; chunk += gridDim.x) {
#pragma unroll 1
        for (int p = 0; p < 4; p++) {
            int n = chunk * 32 + w * 4 + p;
            const float* row = feat_in + (size_t)n * DIM;
            float x[8];
#pragma unroll
            for (int i = 0; i < 8; i++) x[i] = row[lane + 32 * i];
            float s = 0.f, ss = 0.f;
#pragma unroll
            for (int i = 0; i < 8; i++) { s += x[i]; ss += x[i] * x[i]; }
            s = wsum(s); ss = wsum(ss);
            float mu = s * (1.f / DIM);
            float var = ss * (1.f / DIM) - mu * mu;
            float rstd = rsqrtf(var + 1e-5f);
            float nrm = 0.f;
#pragma unroll
            for (int i = 0; i < 8; i++) {
                x[i] = (x[i] - mu) * rstd * sg[lane + 32 * i] + sb[lane + 32 * i];
                nrm += x[i] * x[i];
            }
            nrm = wsum(nrm);
            float inv = 1.0f / fmaxf(sqrtf(nrm), 1e-12f);
#pragma unroll
            for (int i = 0; i < 8; i++) x[i] *= inv;

            float dot[8];
#pragma unroll
            for (int j = 0; j < 8; j++) {
                float d = 0.f;
#pragma unroll
                for (int i = 0; i < 8; i++) d += x[i] * sprot[j][lane + 32 * i];
                dot[j] = wsum(d);             // every lane holds the full dot
            }

            // proto_logits[n, m*4+k] = sim[n,m,k] = dot[k*2+m]; lane j writes slot j
            if (lane < 8) {
                int k = lane & 3, m = lane >> 2;
                logits[(size_t)n * 8 + lane] = dot[k * 2 + m];
            }

            if (lane == 0) {
                float nr[4], no[4];
#pragma unroll
                for (int k = 0; k < 4; k++) nr[k] = fmaxf(dot[2 * k], dot[2 * k + 1]);
                float m4 = 0.25f * (nr[0] + nr[1] + nr[2] + nr[3]);
                float v4 = 0.25f * (nr[0]*nr[0] + nr[1]*nr[1] + nr[2]*nr[2] + nr[3]*nr[3]) - m4 * m4;
                float r4 = rsqrtf(v4 + 1e-5f);
#pragma unroll
                for (int k = 0; k < 4; k++) no[k] = (nr[k] - m4) * r4 * smg[k] + smb[k];
                int pred = 0; float best = no[0];
#pragma unroll
                for (int k = 1; k < 4; k++) if (no[k] > best) { best = no[k]; pred = k; }
                int c = label[n];
                g_correct[n] = (unsigned char)(pred == c);
#pragma unroll
                for (int k = 0; k < 4; k++) stage[k][w * 4 + p] = no[k];
                double e0 = exp((double)dot[c * 2 + 0] * 20.0);   // /SK_EPS
                double e1 = exp((double)dot[c * 2 + 1] * 20.0);
                atomicAdd(&ss1[c][0], e0);
                atomicAdd(&ss1[c][1], e1);
                atomicAdd(&sbn[c], 1);
            }
        }
        __syncthreads();
        // nearest_img[b,k,h,w]: 32-pixel chunks never cross b (32 | 12544)
        if (tid < 128) {
            int k = tid >> 5, i = tid & 31;
            int base = chunk * 32;
            int b = base / IMG;
            int off = base - b * IMG + i;
            out[(size_t)b * 4 * IMG + (size_t)k * IMG + off] = stage[k][i];
        }
        __syncthreads();
    }
    if (tid < 8) atomicAdd(&((double*)g_s)[tid], ((double*)ss1)[tid]);
    if (tid < 4) atomicAdd(&g_Bn[tid], sbn[tid]);
}

// ---------------- K_alpha: row rescale after each iteration ----------------
__global__ void k_alpha(int stage) {
    int c = threadIdx.x;
    if (c >= NCLS) return;
    double s0 = g_s[stage][c][0], s1 = g_s[stage][c][1];
    double ap0, ap1;
    if (stage == 0) {
        double S = s0 + s1;                    // initial L /= max(sum(L),1e-30)
        double a0 = 1.0 / fmax(S, 1e-30);
        ap0 = a0; ap1 = a0;
    } else {
        ap0 = g_alpha[stage - 1][c][0];
        ap1 = g_alpha[stage - 1][c][1];
    }
    g_alpha[stage][c][0] = ap0 / fmax(ap0 * s0, 1e-30) * 0.5;   // /M
    g_alpha[stage][c][1] = ap1 / fmax(ap1 * s1, 1e-30) * 0.5;
}

// ---------------- K_iter: row-sum reductions for sinkhorn iters 2,3 ----------------
__global__ void __launch_bounds__(256) k_iter(
    int stage, const int* __restrict__ label, const float* __restrict__ logits)
{
    __shared__ double sacc[NCLS][NSUB];
    __shared__ double sa1[NCLS][2], sa2[NCLS][2], sbnv[NCLS];
    int tid = threadIdx.x;
    if (tid < 8) {
        ((double*)sacc)[tid] = 0.0;
        ((double*)sa1)[tid] = ((double*)g_alpha)[tid];          // g_alpha[0]
        ((double*)sa2)[tid] = ((double*)g_alpha)[8 + tid];      // g_alpha[1]
    }
    if (tid < NCLS) sbnv[tid] = fmax((double)g_Bn[tid], 1.0);
    __syncthreads();

    int stride = gridDim.x * blockDim.x;
    for (int n = blockIdx.x * blockDim.x + tid; n < NPIX; n += stride) {
        int c = label[n];
        float s0 = logits[(size_t)n * 8 + c];
        float s1 = logits[(size_t)n * 8 + 4 + c];
        double e0 = exp((double)s0 * 20.0), e1 = exp((double)s1 * 20.0);
        double bn = sbnv[c];
        double t1 = e0 * sa1[c][0] + e1 * sa1[c][1];
        double beta = (1.0 / fmax(t1, 1e-30)) / bn;             // beta1
        if (stage == 2) {
            double t2 = e0 * sa2[c][0] + e1 * sa2[c][1];
            beta = beta / fmax(beta * t2, 1e-30) / bn;          // beta2
        }
        atomicAdd(&sacc[c][0], e0 * beta);
        atomicAdd(&sacc[c][1], e1 * beta);
    }
    __syncthreads();
    if (tid < 8) atomicAdd(&((double*)g_s)[stage * 8 + tid], ((double*)sacc)[tid]);
}

// ---------------- K_target: proto_target = idx + NSUB*c ----------------
__global__ void k_target(const int* __restrict__ label, const float* __restrict__ logits,
                         float* __restrict__ target)
{
    int n = blockIdx.x * blockDim.x + threadIdx.x;
    if (n >= NPIX) return;
    int c = label[n];
    float s0 = logits[(size_t)n * 8 + c];
    float s1 = logits[(size_t)n * 8 + 4 + c];
    double e0 = exp((double)s0 * 20.0) * g_alpha[2][c][0];
    double e1 = exp((double)s1 * 20.0) * g_alpha[2][c][1];
    int idx = (e1 > e0) ? 1 : 0;                                // argmax, ties -> 0
    target[n] = (float)(idx + 2 * c);
}

// ---------------- K_accum: masked feature sums (only correct pixels) ----------------
__global__ void __launch_bounds__(256) k_accum(
    const float* __restrict__ feat_in, const int* __restrict__ label,
    const float* __restrict__ fg, const float* __restrict__ fb,
    const float* __restrict__ logits)
{
    __shared__ float sfacc[8][DIM];
    __shared__ int   scnt[8];
    __shared__ float sg[DIM], sb[DIM];
    int tid = threadIdx.x;
    sg[tid] = fg[tid]; sb[tid] = fb[tid];
    for (int t = tid; t < 8 * DIM; t += 256) ((float*)sfacc)[t] = 0.f;
    if (tid < 8) scnt[tid] = 0;
    __syncthreads();

    int w = tid >> 5, lane = tid & 31;
    int gw = blockIdx.x * 8 + w;
    int nw = gridDim.x * 8;

    for (int n = gw; n < NPIX; n += nw) {
        if (!g_correct[n]) continue;
        int c = 0, idx = 0;
        if (lane == 0) {
            c = label[n];
            float s0 = logits[(size_t)n * 8 + c];
            float s1 = logits[(size_t)n * 8 + 4 + c];
            double e0 = exp((double)s0 * 20.0) * g_alpha[2][c][0];
            double e1 = exp((double)s1 * 20.0) * g_alpha[2][c][1];
            idx = (e1 > e0) ? 1 : 0;
        }
        c   = __shfl_sync(0xffffffffu, c, 0);
        idx = __shfl_sync(0xffffffffu, idx, 0);

        const float* row = feat_in + (size_t)n * DIM;
        float x[8];
#pragma unroll
        for (int i = 0; i < 8; i++) x[i] = row[lane + 32 * i];
        float s = 0.f, ss = 0.f;
#pragma unroll
        for (int i = 0; i < 8; i++) { s += x[i]; ss += x[i] * x[i]; }
        s = wsum(s); ss = wsum(ss);
        float mu = s * (1.f / DIM), var = ss * (1.f / DIM) - mu * mu;
        float rstd = rsqrtf(var + 1e-5f);
        float nrm = 0.f;
#pragma unroll
        for (int i = 0; i < 8; i++) {
            x[i] = (x[i] - mu) * rstd * sg[lane + 32 * i] + sb[lane + 32 * i];
            nrm += x[i] * x[i];
        }
        nrm = wsum(nrm);
        float inv = 1.f / fmaxf(sqrtf(nrm), 1e-12f);
        int r = c * 2 + idx;
#pragma unroll
        for (int i = 0; i < 8; i++) atomicAdd(&sfacc[r][lane + 32 * i], x[i] * inv);
        if (lane == 0) atomicAdd(&scnt[r], 1);
    }
    __syncthreads();
    for (int t = tid; t < 8 * DIM; t += 256) atomicAdd(&((float*)g_facc)[t], ((float*)sfacc)[t]);
    if (tid < 8) atomicAdd(&g_cnt[tid], scnt[tid]);
}

// ---------------- K_final: EMA update + renormalize prototypes ----------------
__global__ void k_final(float* __restrict__ out) {
    int tid = threadIdx.x;
    int r = tid >> 5, lane = tid & 31;
    float f[8]; float ss = 0.f;
#pragma unroll
    for (int i = 0; i < 8; i++) { f[i] = g_facc[r][lane + 32 * i]; ss += f[i] * f[i]; }
    ss = wsum(ss);
    float inv = 1.f / fmaxf(sqrtf(ss), 1e-12f);
    int c = r >> 1;
    bool cond = ((g_cnt[c * 2] + g_cnt[c * 2 + 1]) > 0) && (g_cnt[r] != 0);
    float u[8]; float ss2 = 0.f;
#pragma unroll
    for (int i = 0; i < 8; i++) {
        float p = g_protos[r][lane + 32 * i];
        u[i] = cond ? (0.999f * p + 0.001f * (f[i] * inv)) : p;
        ss2 += u[i] * u[i];
    }
    ss2 = wsum(ss2);
    float inv2 = 1.f / fmaxf(sqrtf(ss2), 1e-12f);
    float* np = out + OUT_PROTOS;
#pragma unroll
    for (int i = 0; i < 8; i++) np[r * DIM + lane + 32 * i] = u[i] * inv2;
}

// ---------------- launch ----------------
extern "C" void kernel_launch(void* const* d_in, const int* in_sizes, int n_in,
                              void* d_out, int out_size)
{
    const float* feat   = (const float*)d_in[0];
    const int*   label  = (const int*)  d_in[1];   // JAX canonicalizes int64 -> int32
    const float* protos = (const float*)d_in[2];
    const float* fg     = (const float*)d_in[3];
    const float* fb     = (const float*)d_in[4];
    const float* mg     = (const float*)d_in[5];
    const float* mb     = (const float*)d_in[6];
    float* out = (float*)d_out;

    k_init<<<1, 256>>>(protos);
    k_main<<<1184, 256>>>(feat, label, fg, fb, mg, mb, out);
    k_alpha<<<1, 32>>>(0);
    k_iter<<<1184, 256>>>(1, label, out + OUT_LOGITS);
    k_alpha<<<1, 32>>>(1);
    k_iter<<<1184, 256>>>(2, label, out + OUT_LOGITS);
    k_alpha<<<1, 32>>>(2);
    k_target<<<(NPIX + 255) / 256, 256>>>(label, out + OUT_LOGITS, out + OUT_TARGET);
    k_accum<<<592, 256>>>(feat, label, fg, fb, out + OUT_LOGITS);
    k_final<<<1, 256>>>(out);
}

// round 7
// speedup vs baseline: 2.8124x; 2.8124x over previous
#include <cuda_runtime.h>
#include <math.h>

// Geometry (fixed by the problem)
#define NPIX   401408        // 32*112*112
#define DIM    256
#define NCLS   4
#define NSUB   2
#define IMG    12544         // 112*112

// d_out layout: nearest_img | proto_logits | proto_target | new_protos
#define OUT_LOGITS  (NPIX * NCLS)                 // 1605632
#define OUT_TARGET  (OUT_LOGITS + NPIX * 8)       // 4816896
#define OUT_PROTOS  (OUT_TARGET + NPIX)           // 5218304

// ---------------- device scratch (no allocation allowed) ----------------
__device__ double        g_s[3][NCLS][NSUB];     // exp-sum reductions per sinkhorn iter
__device__ double        g_alpha[3][NCLS][NSUB]; // row scalings after each iteration
__device__ int           g_Bn[NCLS];             // per-class pixel counts
__device__ float         g_facc[8][DIM];         // masked feature sums [c*2+m][d]
__device__ int           g_cnt[8];               // assignment counts  [c*2+m]
__device__ float         g_protos[8][DIM];       // l2-normalized prototypes, row = k*2+m
__device__ unsigned char g_correct[NPIX];

__device__ __forceinline__ float wsum(float v) {
#pragma unroll
    for (int o = 16; o; o >>= 1) v += __shfl_xor_sync(0xffffffffu, v, o);
    return v;
}

// ---------------- K0: zero scratch + normalize prototypes ----------------
__global__ void k_init(const float* __restrict__ protos) {
    int tid = threadIdx.x;
    if (tid < 24) ((double*)g_s)[tid] = 0.0;
    if (tid < NCLS) g_Bn[tid] = 0;
    if (tid < 8)    g_cnt[tid] = 0;
    for (int t = tid; t < 8 * DIM; t += blockDim.x) ((float*)g_facc)[t] = 0.f;

    int w = tid >> 5, lane = tid & 31;
    float p[8]; float ss = 0.f;
#pragma unroll
    for (int i = 0; i < 8; i++) { p[i] = protos[w * DIM + lane + 32 * i]; ss += p[i] * p[i]; }
    ss = wsum(ss);
    float inv = 1.0f / fmaxf(sqrtf(ss), 1e-12f);
#pragma unroll
    for (int i = 0; i < 8; i++) g_protos[w][lane + 32 * i] = p[i] * inv;
}

// ---------------- K1: main fused pass over out_feat ----------------
__global__ void __launch_bounds__(256) k_main(
    const float* __restrict__ feat_in, const int* __restrict__ label,
    const float* __restrict__ fg, const float* __restrict__ fb,
    const float* __restrict__ mg, const float* __restrict__ mb,
    float* __restrict__ out)
{
    __shared__ float  sprot[8][DIM];
    __shared__ float  smg[4], smb[4];
    __shared__ float  stage[4][32];
    __shared__ double ss1[8];
    __shared__ int    sbn[NCLS];

    int tid = threadIdx.x;
    for (int t = tid; t < 8 * DIM; t += 256) ((float*)sprot)[t] = ((const float*)g_protos)[t];
    if (tid < 4) { smg[tid] = mg[tid]; smb[tid] = mb[tid]; sbn[tid] = 0; }
    if (tid < 8) ss1[tid] = 0.0;

    int w = tid >> 5, lane = tid & 31;

    // per-lane gamma/beta in registers (indices 4*lane.., 128+4*lane..)
    const float4* fg4 = (const float4*)fg;
    const float4* fb4 = (const float4*)fb;
    float4 ga = fg4[lane], gb = fg4[lane + 32];
    float4 ba = fb4[lane], bb = fb4[lane + 32];
    float g[8]  = {ga.x, ga.y, ga.z, ga.w, gb.x, gb.y, gb.z, gb.w};
    float be[8] = {ba.x, ba.y, ba.z, ba.w, bb.x, bb.y, bb.z, bb.w};
    __syncthreads();

    float* logits = out + OUT_LOGITS;
    const int nchunks = NPIX / 32;

    for (int chunk = blockIdx.x; chunk < nchunks; chunk += gridDim.x) {
#pragma unroll 1
        for (int p = 0; p < 4; p++) {
            int n = chunk * 32 + w * 4 + p;
            const float4* row4 = (const float4*)(feat_in + (size_t)n * DIM);
            float4 va = row4[lane], vb = row4[lane + 32];
            float x[8] = {va.x, va.y, va.z, va.w, vb.x, vb.y, vb.z, vb.w};
            float s = 0.f, ss = 0.f;
#pragma unroll
            for (int i = 0; i < 8; i++) { s += x[i]; ss += x[i] * x[i]; }
            s = wsum(s); ss = wsum(ss);
            float mu = s * (1.f / DIM);
            float var = ss * (1.f / DIM) - mu * mu;
            float rstd = rsqrtf(var + 1e-5f);
            float nrm = 0.f;
#pragma unroll
            for (int i = 0; i < 8; i++) {
                x[i] = (x[i] - mu) * rstd * g[i] + be[i];
                nrm += x[i] * x[i];
            }
            nrm = wsum(nrm);
            float inv = 1.0f / fmaxf(sqrtf(nrm), 1e-12f);
#pragma unroll
            for (int i = 0; i < 8; i++) x[i] *= inv;

            float dot[8];
#pragma unroll
            for (int j = 0; j < 8; j++) {
                const float4* p4 = (const float4*)sprot[j];
                float4 pa = p4[lane], pb = p4[lane + 32];
                float d = x[0]*pa.x + x[1]*pa.y + x[2]*pa.z + x[3]*pa.w
                        + x[4]*pb.x + x[5]*pb.y + x[6]*pb.z + x[7]*pb.w;
                dot[j] = wsum(d);             // every lane holds the full dot
            }

            // proto_logits[n, m*4+k] = sim[n,m,k] = dot[k*2+m]; lane j writes slot j
            if (lane < 8) {
                int k = lane & 3, m = lane >> 2;
                logits[(size_t)n * 8 + lane] = dot[k * 2 + m];
            }

            if (lane == 0) {
                float nr[4], no[4];
#pragma unroll
                for (int k = 0; k < 4; k++) nr[k] = fmaxf(dot[2 * k], dot[2 * k + 1]);
                float m4 = 0.25f * (nr[0] + nr[1] + nr[2] + nr[3]);
                float v4 = 0.25f * (nr[0]*nr[0] + nr[1]*nr[1] + nr[2]*nr[2] + nr[3]*nr[3]) - m4 * m4;
                float r4 = rsqrtf(v4 + 1e-5f);
#pragma unroll
                for (int k = 0; k < 4; k++) no[k] = (nr[k] - m4) * r4 * smg[k] + smb[k];
                int pred = 0; float best = no[0];
#pragma unroll
                for (int k = 1; k < 4; k++) if (no[k] > best) { best = no[k]; pred = k; }
                int c = label[n];
                g_correct[n] = (unsigned char)(pred == c);
#pragma unroll
                for (int k = 0; k < 4; k++) stage[k][w * 4 + p] = no[k];
                float e0 = expf(dot[c * 2 + 0] * 20.0f);   // /SK_EPS
                float e1 = expf(dot[c * 2 + 1] * 20.0f);
                atomicAdd(&ss1[c * 2 + 0], (double)e0);
                atomicAdd(&ss1[c * 2 + 1], (double)e1);
                atomicAdd(&sbn[c], 1);
            }
        }
        __syncthreads();
        // nearest_img[b,k,h,w]: 32-pixel chunks never cross b (32 | 12544)
        if (tid < 128) {
            int k = tid >> 5, i = tid & 31;
            int base = chunk * 32;
            int b = base / IMG;
            int off = base - b * IMG + i;
            out[(size_t)b * 4 * IMG + (size_t)k * IMG + off] = stage[k][i];
        }
        __syncthreads();
    }
    if (tid < 8) atomicAdd(&((double*)g_s)[tid], ss1[tid]);
    if (tid < 4) atomicAdd(&g_Bn[tid], sbn[tid]);
}

// ---------------- K_alpha: row rescale after each iteration ----------------
__global__ void k_alpha(int stage) {
    int c = threadIdx.x;
    if (c >= NCLS) return;
    double s0 = g_s[stage][c][0], s1 = g_s[stage][c][1];
    double ap0, ap1;
    if (stage == 0) {
        double S = s0 + s1;                    // initial L /= max(sum(L),1e-30)
        double a0 = 1.0 / fmax(S, 1e-30);
        ap0 = a0; ap1 = a0;
    } else {
        ap0 = g_alpha[stage - 1][c][0];
        ap1 = g_alpha[stage - 1][c][1];
    }
    g_alpha[stage][c][0] = ap0 / fmax(ap0 * s0, 1e-30) * 0.5;   // /M
    g_alpha[stage][c][1] = ap1 / fmax(ap1 * s1, 1e-30) * 0.5;
}

// ---------------- K_iter: row-sum reductions for sinkhorn iters 2,3 ----------------
__global__ void __launch_bounds__(256) k_iter(
    int stage, const int* __restrict__ label, const float* __restrict__ logits)
{
    __shared__ double sacc[NCLS][NSUB];
    __shared__ double sa1[NCLS][2], sa2[NCLS][2], sbnv[NCLS];
    int tid = threadIdx.x;
    if (tid < 8) {
        ((double*)sacc)[tid] = 0.0;
        ((double*)sa1)[tid] = ((double*)g_alpha)[tid];          // g_alpha[0]
        ((double*)sa2)[tid] = ((double*)g_alpha)[8 + tid];      // g_alpha[1]
    }
    if (tid < NCLS) sbnv[tid] = fmax((double)g_Bn[tid], 1.0);
    __syncthreads();

    int stride = gridDim.x * blockDim.x;
    for (int n = blockIdx.x * blockDim.x + tid; n < NPIX; n += stride) {
        int c = label[n];
        float s0 = logits[(size_t)n * 8 + c];
        float s1 = logits[(size_t)n * 8 + 4 + c];
        double e0 = (double)expf(s0 * 20.0f), e1 = (double)expf(s1 * 20.0f);
        double bn = sbnv[c];
        double t1 = e0 * sa1[c][0] + e1 * sa1[c][1];
        double beta = (1.0 / fmax(t1, 1e-30)) / bn;             // beta1
        if (stage == 2) {
            double t2 = e0 * sa2[c][0] + e1 * sa2[c][1];
            beta = beta / fmax(beta * t2, 1e-30) / bn;          // beta2
        }
        atomicAdd(&sacc[c][0], e0 * beta);
        atomicAdd(&sacc[c][1], e1 * beta);
    }
    __syncthreads();
    if (tid < 8) atomicAdd(&((double*)g_s)[stage * 8 + tid], ((double*)sacc)[tid]);
}

// ---------------- K_target: proto_target = idx + NSUB*c ----------------
__global__ void k_target(const int* __restrict__ label, const float* __restrict__ logits,
                         float* __restrict__ target)
{
    int n = blockIdx.x * blockDim.x + threadIdx.x;
    if (n >= NPIX) return;
    int c = label[n];
    float s0 = logits[(size_t)n * 8 + c];
    float s1 = logits[(size_t)n * 8 + 4 + c];
    double e0 = (double)expf(s0 * 20.0f) * g_alpha[2][c][0];
    double e1 = (double)expf(s1 * 20.0f) * g_alpha[2][c][1];
    int idx = (e1 > e0) ? 1 : 0;                                // argmax, ties -> 0
    target[n] = (float)(idx + 2 * c);
}

// ---------------- K_accum: masked feature sums (only correct pixels) ----------------
__global__ void __launch_bounds__(256) k_accum(
    const float* __restrict__ feat_in, const int* __restrict__ label,
    const float* __restrict__ fg, const float* __restrict__ fb,
    const float* __restrict__ logits)
{
    __shared__ float sfacc[8][DIM];
    __shared__ int   scnt[8];
    int tid = threadIdx.x;
    for (int t = tid; t < 8 * DIM; t += 256) ((float*)sfacc)[t] = 0.f;
    if (tid < 8) scnt[tid] = 0;

    int w = tid >> 5, lane = tid & 31;
    const float4* fg4 = (const float4*)fg;
    const float4* fb4 = (const float4*)fb;
    float4 ga = fg4[lane], gb = fg4[lane + 32];
    float4 ba = fb4[lane], bb = fb4[lane + 32];
    float g[8]  = {ga.x, ga.y, ga.z, ga.w, gb.x, gb.y, gb.z, gb.w};
    float be[8] = {ba.x, ba.y, ba.z, ba.w, bb.x, bb.y, bb.z, bb.w};
    __syncthreads();

    int gw = blockIdx.x * 8 + w;
    int nw = gridDim.x * 8;

    for (int n = gw; n < NPIX; n += nw) {
        if (!g_correct[n]) continue;
        int c = 0, idx = 0;
        if (lane == 0) {
            c = label[n];
            float s0 = logits[(size_t)n * 8 + c];
            float s1 = logits[(size_t)n * 8 + 4 + c];
            double e0 = (double)expf(s0 * 20.0f) * g_alpha[2][c][0];
            double e1 = (double)expf(s1 * 20.0f) * g_alpha[2][c][1];
            idx = (e1 > e0) ? 1 : 0;
        }
        c   = __shfl_sync(0xffffffffu, c, 0);
        idx = __shfl_sync(0xffffffffu, idx, 0);

        const float4* row4 = (const float4*)(feat_in + (size_t)n * DIM);
        float4 va = row4[lane], vb = row4[lane + 32];
        float x[8] = {va.x, va.y, va.z, va.w, vb.x, vb.y, vb.z, vb.w};
        float s = 0.f, ss = 0.f;
#pragma unroll
        for (int i = 0; i < 8; i++) { s += x[i]; ss += x[i] * x[i]; }
        s = wsum(s); ss = wsum(ss);
        float mu = s * (1.f / DIM), var = ss * (1.f / DIM) - mu * mu;
        float rstd = rsqrtf(var + 1e-5f);
        float nrm = 0.f;
#pragma unroll
        for (int i = 0; i < 8; i++) {
            x[i] = (x[i] - mu) * rstd * g[i] + be[i];
            nrm += x[i] * x[i];
        }
        nrm = wsum(nrm);
        float inv = 1.f / fmaxf(sqrtf(nrm), 1e-12f);
        int r = c * 2 + idx;
        // lane i accumulates smem indices 4*lane.., 128+4*lane..
#pragma unroll
        for (int i = 0; i < 4; i++) atomicAdd(&sfacc[r][4 * lane + i], x[i] * inv);
#pragma unroll
        for (int i = 0; i < 4; i++) atomicAdd(&sfacc[r][128 + 4 * lane + i], x[4 + i] * inv);
        if (lane == 0) atomicAdd(&scnt[r], 1);
    }
    __syncthreads();
    for (int t = tid; t < 8 * DIM; t += 256) atomicAdd(&((float*)g_facc)[t], ((float*)sfacc)[t]);
    if (tid < 8) atomicAdd(&g_cnt[tid], scnt[tid]);
}

// ---------------- K_final: EMA update + renormalize prototypes ----------------
__global__ void k_final(float* __restrict__ out) {
    int tid = threadIdx.x;
    int r = tid >> 5, lane = tid & 31;
    float f[8]; float ss = 0.f;
#pragma unroll
    for (int i = 0; i < 8; i++) { f[i] = g_facc[r][lane + 32 * i]; ss += f[i] * f[i]; }
    ss = wsum(ss);
    float inv = 1.f / fmaxf(sqrtf(ss), 1e-12f);
    int c = r >> 1;
    bool cond = ((g_cnt[c * 2] + g_cnt[c * 2 + 1]) > 0) && (g_cnt[r] != 0);
    float u[8]; float ss2 = 0.f;
#pragma unroll
    for (int i = 0; i < 8; i++) {
        float p = g_protos[r][lane + 32 * i];
        u[i] = cond ? (0.999f * p + 0.001f * (f[i] * inv)) : p;
        ss2 += u[i] * u[i];
    }
    ss2 = wsum(ss2);
    float inv2 = 1.f / fmaxf(sqrtf(ss2), 1e-12f);
    float* np = out + OUT_PROTOS;
#pragma unroll
    for (int i = 0; i < 8; i++) np[r * DIM + lane + 32 * i] = u[i] * inv2;
}

// ---------------- launch ----------------
extern "C" void kernel_launch(void* const* d_in, const int* in_sizes, int n_in,
                              void* d_out, int out_size)
{
    const float* feat   = (const float*)d_in[0];
    const int*   label  = (const int*)  d_in[1];
    const float* protos = (const float*)d_in[2];
    const float* fg     = (const float*)d_in[3];
    const float* fb     = (const float*)d_in[4];
    const float* mg     = (const float*)d_in[5];
    const float* mb     = (const float*)d_in[6];
    float* out = (float*)d_out;

    k_init<<<1, 256>>>(protos);
    k_main<<<1184, 256>>>(feat, label, fg, fb, mg, mb, out);
    k_alpha<<<1, 32>>>(0);
    k_iter<<<1184, 256>>>(1, label, out + OUT_LOGITS);
    k_alpha<<<1, 32>>>(1);
    k_iter<<<1184, 256>>>(2, label, out + OUT_LOGITS);
    k_alpha<<<1, 32>>>(2);
    k_target<<<(NPIX + 255) / 256, 256>>>(label, out + OUT_LOGITS, out + OUT_TARGET);
    k_accum<<<592, 256>>>(feat, label, fg, fb, out + OUT_LOGITS);
    k_final<<<1, 256>>>(out);
}